// round 5
// baseline (speedup 1.0000x reference)
#include <cuda_runtime.h>

#define N_NODES 40000
#define N_EDGES 640000
#define D 128

// ---- device scratch (static globals: allocation-free kernel_launch) ----
__device__ int   g_deg[N_NODES];
__device__ int   g_start[N_NODES];
__device__ int   g_cursor[N_NODES];
__device__ int   g_csr[N_EDGES];
__device__ float g_hneigh[N_NODES * D];   // ~20.5 MB

// ---------------------------------------------------------------- zero deg
__global__ void k_zero_deg() {
    int i = blockIdx.x * blockDim.x + threadIdx.x;
    if (i < N_NODES) g_deg[i] = 0;
}

// ---------------------------------------------------------------- degrees
__global__ void k_degree(const int* __restrict__ dst) {
    int e = blockIdx.x * blockDim.x + threadIdx.x;
    if (e < N_EDGES) atomicAdd(&g_deg[dst[e]], 1);
}

// ---------------------------------------------------------------- scan (1 block)
__global__ void k_scan() {
    __shared__ int sm[1024];
    const int CH = 40;                       // 1024 * 40 = 40960 >= 40000
    int t = threadIdx.x;
    int begin = t * CH;
    int s = 0;
#pragma unroll
    for (int i = 0; i < CH; i++) {
        int idx = begin + i;
        if (idx < N_NODES) s += g_deg[idx];
    }
    sm[t] = s;
    __syncthreads();
    for (int off = 1; off < 1024; off <<= 1) {
        int v = (t >= off) ? sm[t - off] : 0;
        __syncthreads();
        sm[t] += v;
        __syncthreads();
    }
    int run = sm[t] - s;                     // exclusive base
    for (int i = 0; i < CH; i++) {
        int idx = begin + i;
        if (idx < N_NODES) {
            g_start[idx]  = run;
            g_cursor[idx] = run;
            run += g_deg[idx];
        }
    }
}

// ---------------------------------------------------------------- scatter into CSR
__global__ void k_scatter(const int* __restrict__ src, const int* __restrict__ dst) {
    int e = blockIdx.x * blockDim.x + threadIdx.x;
    if (e < N_EDGES) {
        int p = atomicAdd(&g_cursor[dst[e]], 1);
        g_csr[p] = src[e];
    }
}

// ---------------------------------------------------------------- aggregate: 1 warp / node
__global__ void k_aggregate(const float4* __restrict__ feat4) {
    int warp = (blockIdx.x * blockDim.x + threadIdx.x) >> 5;
    int lane = threadIdx.x & 31;
    if (warp >= N_NODES) return;

    int s0 = g_start[warp];
    int d  = g_deg[warp];

    float4 acc = make_float4(0.f, 0.f, 0.f, 0.f);
    int t = 0;
    for (; t + 2 <= d; t += 2) {
        int n0 = g_csr[s0 + t];
        int n1 = g_csr[s0 + t + 1];
        float4 v0 = feat4[n0 * 32 + lane];
        float4 v1 = feat4[n1 * 32 + lane];
        acc.x += v0.x; acc.y += v0.y; acc.z += v0.z; acc.w += v0.w;
        acc.x += v1.x; acc.y += v1.y; acc.z += v1.z; acc.w += v1.w;
    }
    if (t < d) {
        int n0 = g_csr[s0 + t];
        float4 v0 = feat4[n0 * 32 + lane];
        acc.x += v0.x; acc.y += v0.y; acc.z += v0.z; acc.w += v0.w;
    }
    float sc = 1.0f / (float)(d > 0 ? d : 1);
    acc.x *= sc; acc.y *= sc; acc.z *= sc; acc.w *= sc;
    reinterpret_cast<float4*>(g_hneigh)[warp * 32 + lane] = acc;
}

// ---------------------------------------------------------------- fused GEMM
// out[n, j] = sum_k feat[n,k]*W_self[k,j] + sum_k h_neigh[n,k]*W_neigh[k,j] + bias[j]
// Persistent blocks, W (256x128) + bias staged once, X tile (32x256) per tile.
// 256 threads: tx=tid&31 -> 4 output cols, ty=tid>>5 -> 4 nodes, 4x4 register block.
#define TILE_M   32
#define N_TILES  (N_NODES / TILE_M)          // 1250 exactly
#define KK       (2 * D)                      // 256
#define GEMM_SMEM_BYTES ((KK * D + TILE_M * KK + D) * 4)

__global__ void __launch_bounds__(256, 1)
k_gemm(const float* __restrict__ feat,
       const float* __restrict__ W_self,  const float* __restrict__ b_self,
       const float* __restrict__ W_neigh, const float* __restrict__ b_neigh,
       float* __restrict__ out) {
    extern __shared__ float smem[];
    float* sW = smem;                 // [256][128]
    float* sX = sW + KK * D;          // [32][256]  (Xs[m][k])
    float* sB = sX + TILE_M * KK;     // [128]

    int tid = threadIdx.x;

    // stage weights once (combined [k][j], k<128 self, k>=128 neigh)
    for (int idx = tid; idx < KK * D; idx += 256) {
        float v = (idx < D * D) ? W_self[idx] : W_neigh[idx - D * D];
        sW[idx] = v;
    }
    if (tid < D) sB[tid] = b_self[tid] + b_neigh[tid];

    int tx = tid & 31;        // col group
    int ty = tid >> 5;        // node group
    int j0 = tx * 4;
    int m0 = ty * 4;

    for (int tile = blockIdx.x; tile < N_TILES; tile += gridDim.x) {
        int node0 = tile * TILE_M;

        __syncthreads();  // protect sX from previous tile's readers
        // stage X tile: rows = nodes, cols = 256 (feat | h_neigh), coalesced
        for (int idx = tid; idx < TILE_M * KK; idx += 256) {
            int m = idx >> 8;          // / 256
            int k = idx & 255;
            float v = (k < D) ? feat[(node0 + m) * D + k]
                              : g_hneigh[(node0 + m) * D + (k - D)];
            sX[m * KK + k] = v;
        }
        __syncthreads();

        float4 a0 = make_float4(0.f,0.f,0.f,0.f);
        float4 a1 = make_float4(0.f,0.f,0.f,0.f);
        float4 a2 = make_float4(0.f,0.f,0.f,0.f);
        float4 a3 = make_float4(0.f,0.f,0.f,0.f);

#pragma unroll 4
        for (int k = 0; k < KK; ++k) {
            float4 w = *reinterpret_cast<const float4*>(&sW[k * D + j0]);
            float x0 = sX[(m0 + 0) * KK + k];
            float x1 = sX[(m0 + 1) * KK + k];
            float x2 = sX[(m0 + 2) * KK + k];
            float x3 = sX[(m0 + 3) * KK + k];
            a0.x += x0 * w.x; a0.y += x0 * w.y; a0.z += x0 * w.z; a0.w += x0 * w.w;
            a1.x += x1 * w.x; a1.y += x1 * w.y; a1.z += x1 * w.z; a1.w += x1 * w.w;
            a2.x += x2 * w.x; a2.y += x2 * w.y; a2.z += x2 * w.z; a2.w += x2 * w.w;
            a3.x += x3 * w.x; a3.y += x3 * w.y; a3.z += x3 * w.z; a3.w += x3 * w.w;
        }

        float4 b = *reinterpret_cast<const float4*>(&sB[j0]);
        a0.x += b.x; a0.y += b.y; a0.z += b.z; a0.w += b.w;
        a1.x += b.x; a1.y += b.y; a1.z += b.z; a1.w += b.w;
        a2.x += b.x; a2.y += b.y; a2.z += b.z; a2.w += b.w;
        a3.x += b.x; a3.y += b.y; a3.z += b.z; a3.w += b.w;

        *reinterpret_cast<float4*>(&out[(node0 + m0 + 0) * D + j0]) = a0;
        *reinterpret_cast<float4*>(&out[(node0 + m0 + 1) * D + j0]) = a1;
        *reinterpret_cast<float4*>(&out[(node0 + m0 + 2) * D + j0]) = a2;
        *reinterpret_cast<float4*>(&out[(node0 + m0 + 3) * D + j0]) = a3;
    }
}

// ---------------------------------------------------------------- launch
extern "C" void kernel_launch(void* const* d_in, const int* in_sizes, int n_in,
                              void* d_out, int out_size) {
    const float* feat    = (const float*)d_in[0];
    const int*   src     = (const int*)  d_in[1];
    const int*   dst     = (const int*)  d_in[2];
    const float* W_self  = (const float*)d_in[3];
    const float* b_self  = (const float*)d_in[4];
    const float* W_neigh = (const float*)d_in[5];
    const float* b_neigh = (const float*)d_in[6];
    float*       out     = (float*)d_out;

    static bool attr_done = false;
    if (!attr_done) {
        cudaFuncSetAttribute(k_gemm, cudaFuncAttributeMaxDynamicSharedMemorySize,
                             GEMM_SMEM_BYTES);
        attr_done = true;
    }

    k_zero_deg<<<(N_NODES + 255) / 256, 256>>>();
    k_degree  <<<N_EDGES / 256, 256>>>(dst);
    k_scan    <<<1, 1024>>>();
    k_scatter <<<N_EDGES / 256, 256>>>(src, dst);
    k_aggregate<<<N_NODES / 8, 256>>>(reinterpret_cast<const float4*>(feat));
    k_gemm    <<<148, 256, GEMM_SMEM_BYTES>>>(feat, W_self, b_self, W_neigh, b_neigh, out);
}

// round 9
// speedup vs baseline: 1.2739x; 1.2739x over previous
#include <cuda_runtime.h>

#define N_NODES 40000
#define N_EDGES 640000
#define D 128

// ---- device scratch (static globals: allocation-free kernel_launch) ----
__device__ int   g_deg[N_NODES];
__device__ int   g_start[N_NODES];
__device__ int   g_cursor[N_NODES];
__device__ int   g_csr[N_EDGES];
__device__ float g_hneigh[N_NODES * D];   // ~20.5 MB, L2-resident

// ---- packed fp32x2 helpers (FFMA2 path, PTX-only) ----
__device__ __forceinline__ unsigned long long pack_dup(float x) {
    unsigned long long p;
    asm("mov.b64 %0, {%1, %1};" : "=l"(p) : "f"(x));
    return p;
}
__device__ __forceinline__ void fma2(unsigned long long& acc,
                                     unsigned long long a, unsigned long long b) {
    asm("fma.rn.f32x2 %0, %1, %2, %0;" : "+l"(acc) : "l"(a), "l"(b));
}
__device__ __forceinline__ void unpack2(unsigned long long v, float& lo, float& hi) {
    asm("mov.b64 {%0, %1}, %2;" : "=f"(lo), "=f"(hi) : "l"(v));
}

// ---------------------------------------------------------------- zero deg
__global__ void k_zero_deg() {
    int i = blockIdx.x * blockDim.x + threadIdx.x;
    if (i < N_NODES) g_deg[i] = 0;
}

// ---------------------------------------------------------------- degrees (int4, 4 independent REDs)
__global__ void k_degree(const int4* __restrict__ dst4) {
    int i = blockIdx.x * blockDim.x + threadIdx.x;
    if (i < N_EDGES / 4) {
        int4 d = dst4[i];
        atomicAdd(&g_deg[d.x], 1);
        atomicAdd(&g_deg[d.y], 1);
        atomicAdd(&g_deg[d.z], 1);
        atomicAdd(&g_deg[d.w], 1);
    }
}

// ---------------------------------------------------------------- scan (1 block)
__global__ void k_scan() {
    __shared__ int sm[1024];
    const int CH = 40;                       // 1024 * 40 = 40960 >= 40000
    int t = threadIdx.x;
    int begin = t * CH;
    int s = 0;
#pragma unroll
    for (int i = 0; i < CH; i++) {
        int idx = begin + i;
        if (idx < N_NODES) s += g_deg[idx];
    }
    sm[t] = s;
    __syncthreads();
    for (int off = 1; off < 1024; off <<= 1) {
        int v = (t >= off) ? sm[t - off] : 0;
        __syncthreads();
        sm[t] += v;
        __syncthreads();
    }
    int run = sm[t] - s;                     // exclusive base
    for (int i = 0; i < CH; i++) {
        int idx = begin + i;
        if (idx < N_NODES) {
            g_start[idx]  = run;
            g_cursor[idx] = run;
            run += g_deg[idx];
        }
    }
}

// ---------------------------------------------------------------- scatter (int4, 4 independent atomic chains)
__global__ void k_scatter(const int4* __restrict__ src4, const int4* __restrict__ dst4) {
    int i = blockIdx.x * blockDim.x + threadIdx.x;
    if (i < N_EDGES / 4) {
        int4 d = dst4[i];
        int4 s = src4[i];
        int p0 = atomicAdd(&g_cursor[d.x], 1);
        int p1 = atomicAdd(&g_cursor[d.y], 1);
        int p2 = atomicAdd(&g_cursor[d.z], 1);
        int p3 = atomicAdd(&g_cursor[d.w], 1);
        g_csr[p0] = s.x;
        g_csr[p1] = s.y;
        g_csr[p2] = s.z;
        g_csr[p3] = s.w;
    }
}

// ---------------------------------------------------------------- aggregate: 1 warp / node, MLP-4
__global__ void k_aggregate(const float4* __restrict__ feat4) {
    int warp = (blockIdx.x * blockDim.x + threadIdx.x) >> 5;
    int lane = threadIdx.x & 31;
    if (warp >= N_NODES) return;

    int s0 = g_start[warp];
    int d  = g_deg[warp];

    float4 acc = make_float4(0.f, 0.f, 0.f, 0.f);
    int t = 0;
    for (; t + 4 <= d; t += 4) {
        int n0 = g_csr[s0 + t];
        int n1 = g_csr[s0 + t + 1];
        int n2 = g_csr[s0 + t + 2];
        int n3 = g_csr[s0 + t + 3];
        float4 v0 = feat4[n0 * 32 + lane];
        float4 v1 = feat4[n1 * 32 + lane];
        float4 v2 = feat4[n2 * 32 + lane];
        float4 v3 = feat4[n3 * 32 + lane];
        acc.x += v0.x; acc.y += v0.y; acc.z += v0.z; acc.w += v0.w;
        acc.x += v1.x; acc.y += v1.y; acc.z += v1.z; acc.w += v1.w;
        acc.x += v2.x; acc.y += v2.y; acc.z += v2.z; acc.w += v2.w;
        acc.x += v3.x; acc.y += v3.y; acc.z += v3.z; acc.w += v3.w;
    }
    for (; t < d; t++) {
        int n0 = g_csr[s0 + t];
        float4 v0 = feat4[n0 * 32 + lane];
        acc.x += v0.x; acc.y += v0.y; acc.z += v0.z; acc.w += v0.w;
    }
    float sc = 1.0f / (float)(d > 0 ? d : 1);
    acc.x *= sc; acc.y *= sc; acc.z *= sc; acc.w *= sc;
    reinterpret_cast<float4*>(g_hneigh)[warp * 32 + lane] = acc;
}

// ---------------------------------------------------------------- fused GEMM (FFMA2)
// out[n, j] = sum_k X[n,k] * W[k,j] + bias[j], X = [feat | h_neigh], W = [W_self ; W_neigh]
// TILE_M=40 -> 1000 tiles (96.5% wave efficiency at grid=148).
// 256 threads: tx=tid&31 -> 4 cols (as 2 f32x2 pairs), ty=tid>>5 -> 5 rows.
#define TILE_M   40
#define N_TILES  (N_NODES / TILE_M)          // 1000 exactly
#define KK       (2 * D)                      // 256
#define GEMM_SMEM_BYTES ((KK * D + TILE_M * KK + D) * 4)

__global__ void __launch_bounds__(256, 1)
k_gemm(const float4* __restrict__ feat4,
       const float4* __restrict__ W_self4,  const float* __restrict__ b_self,
       const float4* __restrict__ W_neigh4, const float* __restrict__ b_neigh,
       float* __restrict__ out) {
    extern __shared__ float smem[];
    float* sW = smem;                 // [256][128]
    float* sX = sW + KK * D;          // [40][256]
    float* sB = sX + TILE_M * KK;     // [128]

    const float4* hneigh4 = reinterpret_cast<const float4*>(g_hneigh);
    int tid = threadIdx.x;

    // stage weights once (combined [k][j], k<128 self, k>=128 neigh)
    {
        float4* sW4 = reinterpret_cast<float4*>(sW);
        const int nW4 = KK * D / 4;                 // 8192
        for (int idx = tid; idx < nW4; idx += 256)
            sW4[idx] = (idx < D * D / 4) ? W_self4[idx] : W_neigh4[idx - D * D / 4];
    }
    if (tid < D) sB[tid] = b_self[tid] + b_neigh[tid];

    int tx = tid & 31;        // col group
    int ty = tid >> 5;        // node group (0..7)
    int j0 = tx * 4;
    int m0 = ty * 5;

    for (int tile = blockIdx.x; tile < N_TILES; tile += gridDim.x) {
        int node0 = tile * TILE_M;

        __syncthreads();  // protect sX from previous tile's readers
        // stage X tile as float4: idx -> (m = idx>>6, kq = idx&63)
        {
            float4* sX4 = reinterpret_cast<float4*>(sX);
            const int nX4 = TILE_M * KK / 4;        // 2560
            for (int idx = tid; idx < nX4; idx += 256) {
                int m  = idx >> 6;
                int kq = idx & 63;
                float4 v = (kq < 32) ? feat4[(node0 + m) * 32 + kq]
                                     : hneigh4[(node0 + m) * 32 + (kq - 32)];
                sX4[idx] = v;
            }
        }
        __syncthreads();

        unsigned long long a[5][2];
#pragma unroll
        for (int m = 0; m < 5; m++) { a[m][0] = 0ULL; a[m][1] = 0ULL; }

#pragma unroll 2
        for (int kc = 0; kc < KK; kc += 4) {
            float xv[5][4];
#pragma unroll
            for (int m = 0; m < 5; m++)
                *reinterpret_cast<float4*>(xv[m]) =
                    *reinterpret_cast<const float4*>(&sX[(m0 + m) * KK + kc]);
#pragma unroll
            for (int c = 0; c < 4; c++) {
                ulonglong2 w = *reinterpret_cast<const ulonglong2*>(&sW[(kc + c) * D + j0]);
#pragma unroll
                for (int m = 0; m < 5; m++) {
                    unsigned long long xp = pack_dup(xv[m][c]);
                    fma2(a[m][0], xp, w.x);
                    fma2(a[m][1], xp, w.y);
                }
            }
        }

        float4 b = *reinterpret_cast<const float4*>(&sB[j0]);
#pragma unroll
        for (int m = 0; m < 5; m++) {
            float4 r;
            unpack2(a[m][0], r.x, r.y);
            unpack2(a[m][1], r.z, r.w);
            r.x += b.x; r.y += b.y; r.z += b.z; r.w += b.w;
            *reinterpret_cast<float4*>(&out[(node0 + m0 + m) * D + j0]) = r;
        }
    }
}

// ---------------------------------------------------------------- launch
extern "C" void kernel_launch(void* const* d_in, const int* in_sizes, int n_in,
                              void* d_out, int out_size) {
    const float* feat    = (const float*)d_in[0];
    const int*   src     = (const int*)  d_in[1];
    const int*   dst     = (const int*)  d_in[2];
    const float* W_self  = (const float*)d_in[3];
    const float* b_self  = (const float*)d_in[4];
    const float* W_neigh = (const float*)d_in[5];
    const float* b_neigh = (const float*)d_in[6];
    float*       out     = (float*)d_out;

    static bool attr_done = false;
    if (!attr_done) {
        cudaFuncSetAttribute(k_gemm, cudaFuncAttributeMaxDynamicSharedMemorySize,
                             GEMM_SMEM_BYTES);
        attr_done = true;
    }

    k_zero_deg<<<(N_NODES + 255) / 256, 256>>>();
    k_degree  <<<(N_EDGES / 4) / 256, 256>>>(reinterpret_cast<const int4*>(dst));
    k_scan    <<<1, 1024>>>();
    k_scatter <<<(N_EDGES / 4) / 256, 256>>>(reinterpret_cast<const int4*>(src),
                                             reinterpret_cast<const int4*>(dst));
    k_aggregate<<<N_NODES / 8, 256>>>(reinterpret_cast<const float4*>(feat));
    k_gemm    <<<148, 256, GEMM_SMEM_BYTES>>>(reinterpret_cast<const float4*>(feat),
                                              reinterpret_cast<const float4*>(W_self), b_self,
                                              reinterpret_cast<const float4*>(W_neigh), b_neigh,
                                              out);
}

// round 10
// speedup vs baseline: 1.2785x; 1.0036x over previous
#include <cuda_runtime.h>

#define N_NODES 40000
#define N_EDGES 640000
#define D 128

// ---- device scratch (static globals: allocation-free kernel_launch) ----
__device__ int   g_deg[N_NODES];
__device__ int   g_start[N_NODES];
__device__ int   g_cursor[N_NODES];
__device__ int   g_csr[N_EDGES];
__device__ float g_hneigh[N_NODES * D];   // ~20.5 MB, L2-resident

// ---- packed fp32x2 helpers (FFMA2 path, PTX-only) ----
__device__ __forceinline__ unsigned long long pack_dup(float x) {
    unsigned long long p;
    asm("mov.b64 %0, {%1, %1};" : "=l"(p) : "f"(x));
    return p;
}
__device__ __forceinline__ void fma2(unsigned long long& acc,
                                     unsigned long long a, unsigned long long b) {
    asm("fma.rn.f32x2 %0, %1, %2, %0;" : "+l"(acc) : "l"(a), "l"(b));
}
__device__ __forceinline__ void unpack2(unsigned long long v, float& lo, float& hi) {
    asm("mov.b64 {%0, %1}, %2;" : "=f"(lo), "=f"(hi) : "l"(v));
}

// ---------------------------------------------------------------- zero deg
__global__ void k_zero_deg() {
    int i = blockIdx.x * blockDim.x + threadIdx.x;
    if (i < N_NODES) g_deg[i] = 0;
}

// ---------------------------------------------------------------- degrees (int4, 4 independent REDs)
__global__ void k_degree(const int4* __restrict__ dst4) {
    int i = blockIdx.x * blockDim.x + threadIdx.x;
    if (i < N_EDGES / 4) {
        int4 d = dst4[i];
        atomicAdd(&g_deg[d.x], 1);
        atomicAdd(&g_deg[d.y], 1);
        atomicAdd(&g_deg[d.z], 1);
        atomicAdd(&g_deg[d.w], 1);
    }
}

// ---------------------------------------------------------------- scan (1 block)
__global__ void k_scan() {
    __shared__ int sm[1024];
    const int CH = 40;                       // 1024 * 40 = 40960 >= 40000
    int t = threadIdx.x;
    int begin = t * CH;
    int s = 0;
#pragma unroll
    for (int i = 0; i < CH; i++) {
        int idx = begin + i;
        if (idx < N_NODES) s += g_deg[idx];
    }
    sm[t] = s;
    __syncthreads();
    for (int off = 1; off < 1024; off <<= 1) {
        int v = (t >= off) ? sm[t - off] : 0;
        __syncthreads();
        sm[t] += v;
        __syncthreads();
    }
    int run = sm[t] - s;                     // exclusive base
    for (int i = 0; i < CH; i++) {
        int idx = begin + i;
        if (idx < N_NODES) {
            g_start[idx]  = run;
            g_cursor[idx] = run;
            run += g_deg[idx];
        }
    }
}

// ---------------------------------------------------------------- scatter (int4, 4 independent atomic chains)
__global__ void k_scatter(const int4* __restrict__ src4, const int4* __restrict__ dst4) {
    int i = blockIdx.x * blockDim.x + threadIdx.x;
    if (i < N_EDGES / 4) {
        int4 d = dst4[i];
        int4 s = src4[i];
        int p0 = atomicAdd(&g_cursor[d.x], 1);
        int p1 = atomicAdd(&g_cursor[d.y], 1);
        int p2 = atomicAdd(&g_cursor[d.z], 1);
        int p3 = atomicAdd(&g_cursor[d.w], 1);
        g_csr[p0] = s.x;
        g_csr[p1] = s.y;
        g_csr[p2] = s.z;
        g_csr[p3] = s.w;
    }
}

// ---------------------------------------------------------------- aggregate: 1 warp / node, MLP-4
__global__ void k_aggregate(const float4* __restrict__ feat4) {
    int warp = (blockIdx.x * blockDim.x + threadIdx.x) >> 5;
    int lane = threadIdx.x & 31;
    if (warp >= N_NODES) return;

    int s0 = g_start[warp];
    int d  = g_deg[warp];

    float4 acc = make_float4(0.f, 0.f, 0.f, 0.f);
    int t = 0;
    for (; t + 4 <= d; t += 4) {
        int n0 = g_csr[s0 + t];
        int n1 = g_csr[s0 + t + 1];
        int n2 = g_csr[s0 + t + 2];
        int n3 = g_csr[s0 + t + 3];
        float4 v0 = feat4[n0 * 32 + lane];
        float4 v1 = feat4[n1 * 32 + lane];
        float4 v2 = feat4[n2 * 32 + lane];
        float4 v3 = feat4[n3 * 32 + lane];
        acc.x += v0.x; acc.y += v0.y; acc.z += v0.z; acc.w += v0.w;
        acc.x += v1.x; acc.y += v1.y; acc.z += v1.z; acc.w += v1.w;
        acc.x += v2.x; acc.y += v2.y; acc.z += v2.z; acc.w += v2.w;
        acc.x += v3.x; acc.y += v3.y; acc.z += v3.z; acc.w += v3.w;
    }
    for (; t < d; t++) {
        int n0 = g_csr[s0 + t];
        float4 v0 = feat4[n0 * 32 + lane];
        acc.x += v0.x; acc.y += v0.y; acc.z += v0.z; acc.w += v0.w;
    }
    float sc = 1.0f / (float)(d > 0 ? d : 1);
    acc.x *= sc; acc.y *= sc; acc.z *= sc; acc.w *= sc;
    reinterpret_cast<float4*>(g_hneigh)[warp * 32 + lane] = acc;
}

// ---------------------------------------------------------------- fused GEMM (FFMA2)
// out[n, j] = sum_k X[n,k] * W[k,j] + bias[j], X = [feat | h_neigh], W = [W_self ; W_neigh]
// TILE_M=40 -> 1000 tiles (96.5% wave efficiency at grid=148).
// 256 threads: tx=tid&31 -> 4 cols (as 2 f32x2 pairs), ty=tid>>5 -> 5 rows.
#define TILE_M   40
#define N_TILES  (N_NODES / TILE_M)          // 1000 exactly
#define KK       (2 * D)                      // 256
#define GEMM_SMEM_BYTES ((KK * D + TILE_M * KK + D) * 4)

__global__ void __launch_bounds__(256, 1)
k_gemm(const float4* __restrict__ feat4,
       const float4* __restrict__ W_self4,  const float* __restrict__ b_self,
       const float4* __restrict__ W_neigh4, const float* __restrict__ b_neigh,
       float* __restrict__ out) {
    extern __shared__ float smem[];
    float* sW = smem;                 // [256][128]
    float* sX = sW + KK * D;          // [40][256]
    float* sB = sX + TILE_M * KK;     // [128]

    const float4* hneigh4 = reinterpret_cast<const float4*>(g_hneigh);
    int tid = threadIdx.x;

    // stage weights once (combined [k][j], k<128 self, k>=128 neigh)
    {
        float4* sW4 = reinterpret_cast<float4*>(sW);
        const int nW4 = KK * D / 4;                 // 8192
        for (int idx = tid; idx < nW4; idx += 256)
            sW4[idx] = (idx < D * D / 4) ? W_self4[idx] : W_neigh4[idx - D * D / 4];
    }
    if (tid < D) sB[tid] = b_self[tid] + b_neigh[tid];

    int tx = tid & 31;        // col group
    int ty = tid >> 5;        // node group (0..7)
    int j0 = tx * 4;
    int m0 = ty * 5;

    for (int tile = blockIdx.x; tile < N_TILES; tile += gridDim.x) {
        int node0 = tile * TILE_M;

        __syncthreads();  // protect sX from previous tile's readers
        // stage X tile as float4: idx -> (m = idx>>6, kq = idx&63)
        {
            float4* sX4 = reinterpret_cast<float4*>(sX);
            const int nX4 = TILE_M * KK / 4;        // 2560
            for (int idx = tid; idx < nX4; idx += 256) {
                int m  = idx >> 6;
                int kq = idx & 63;
                float4 v = (kq < 32) ? feat4[(node0 + m) * 32 + kq]
                                     : hneigh4[(node0 + m) * 32 + (kq - 32)];
                sX4[idx] = v;
            }
        }
        __syncthreads();

        unsigned long long a[5][2];
#pragma unroll
        for (int m = 0; m < 5; m++) { a[m][0] = 0ULL; a[m][1] = 0ULL; }

#pragma unroll 2
        for (int kc = 0; kc < KK; kc += 4) {
            float xv[5][4];
#pragma unroll
            for (int m = 0; m < 5; m++)
                *reinterpret_cast<float4*>(xv[m]) =
                    *reinterpret_cast<const float4*>(&sX[(m0 + m) * KK + kc]);
#pragma unroll
            for (int c = 0; c < 4; c++) {
                ulonglong2 w = *reinterpret_cast<const ulonglong2*>(&sW[(kc + c) * D + j0]);
#pragma unroll
                for (int m = 0; m < 5; m++) {
                    unsigned long long xp = pack_dup(xv[m][c]);
                    fma2(a[m][0], xp, w.x);
                    fma2(a[m][1], xp, w.y);
                }
            }
        }

        float4 b = *reinterpret_cast<const float4*>(&sB[j0]);
#pragma unroll
        for (int m = 0; m < 5; m++) {
            float4 r;
            unpack2(a[m][0], r.x, r.y);
            unpack2(a[m][1], r.z, r.w);
            r.x += b.x; r.y += b.y; r.z += b.z; r.w += b.w;
            *reinterpret_cast<float4*>(&out[(node0 + m0 + m) * D + j0]) = r;
        }
    }
}

// ---------------------------------------------------------------- launch
extern "C" void kernel_launch(void* const* d_in, const int* in_sizes, int n_in,
                              void* d_out, int out_size) {
    const float* feat    = (const float*)d_in[0];
    const int*   src     = (const int*)  d_in[1];
    const int*   dst     = (const int*)  d_in[2];
    const float* W_self  = (const float*)d_in[3];
    const float* b_self  = (const float*)d_in[4];
    const float* W_neigh = (const float*)d_in[5];
    const float* b_neigh = (const float*)d_in[6];
    float*       out     = (float*)d_out;

    static bool attr_done = false;
    if (!attr_done) {
        cudaFuncSetAttribute(k_gemm, cudaFuncAttributeMaxDynamicSharedMemorySize,
                             GEMM_SMEM_BYTES);
        attr_done = true;
    }

    k_zero_deg<<<(N_NODES + 255) / 256, 256>>>();
    k_degree  <<<(N_EDGES / 4) / 256, 256>>>(reinterpret_cast<const int4*>(dst));
    k_scan    <<<1, 1024>>>();
    k_scatter <<<(N_EDGES / 4) / 256, 256>>>(reinterpret_cast<const int4*>(src),
                                             reinterpret_cast<const int4*>(dst));
    k_aggregate<<<N_NODES / 8, 256>>>(reinterpret_cast<const float4*>(feat));
    k_gemm    <<<148, 256, GEMM_SMEM_BYTES>>>(reinterpret_cast<const float4*>(feat),
                                              reinterpret_cast<const float4*>(W_self), b_self,
                                              reinterpret_cast<const float4*>(W_neigh), b_neigh,
                                              out);
}